// round 11
// baseline (speedup 1.0000x reference)
#include <cuda_runtime.h>
#include <cuda_fp16.h>
#include <cstdint>

#define NQ 4096
#define NK 8192
#define DIM 1024

// ---------------------------------------------------------------------------
// Scratch (device globals; no allocation in kernel_launch)
// ---------------------------------------------------------------------------
__device__ __half g_Qh[(size_t)NQ * DIM];     //  8 MB fp16 Q
__device__ __half g_Kh[(size_t)NK * DIM];     // 16 MB fp16 K (K-major)
__device__ __half g_Vt[(size_t)DIM * NK];     // 16 MB fp16 V^T [n][k]
__device__ __half g_R [(size_t)NQ * NK];      // 64 MB fp16 R = exp(cos)-1
__device__ float  g_qninv[NQ];
__device__ float  g_kninv[NK];
__device__ float  g_rsum[NQ];
__device__ float  g_colsum[DIM];
__device__ float  g_knpart[32][NK];           // per-dim-strip |k|^2 partials
__device__ float  g_colpart[256][DIM];        // per-key-strip colsum partials
__device__ float  g_rpart[NK / 128][NQ];      // per-n-tile row partials (GEMM1)

// ---------------------------------------------------------------------------
// PTX helpers (plain sm_103-compatible: mma.sync / ldmatrix / cp.async)
// ---------------------------------------------------------------------------
__device__ __forceinline__ uint32_t smem_u32(const void* p) {
    uint32_t a;
    asm("{ .reg .u64 t; cvta.to.shared.u64 t, %1; cvt.u32.u64 %0, t; }"
        : "=r"(a) : "l"(p));
    return a;
}
__device__ __forceinline__ void cp16(uint32_t dst, const void* src) {
    asm volatile("cp.async.cg.shared.global [%0], [%1], 16;" :: "r"(dst), "l"(src));
}
#define CP_COMMIT() asm volatile("cp.async.commit_group;" ::: "memory")
#define CP_WAIT(N)  asm volatile("cp.async.wait_group %0;" :: "n"(N) : "memory")

__device__ __forceinline__ void ldsm_x4(uint32_t (&r)[4], uint32_t addr) {
    asm volatile("ldmatrix.sync.aligned.m8n8.x4.shared.b16 {%0,%1,%2,%3}, [%4];"
        : "=r"(r[0]), "=r"(r[1]), "=r"(r[2]), "=r"(r[3]) : "r"(addr));
}
__device__ __forceinline__ void mma16816(float (&d)[4], const uint32_t (&a)[4],
                                         uint32_t b0, uint32_t b1) {
    asm volatile("mma.sync.aligned.m16n8k16.row.col.f32.f16.f16.f32 "
        "{%0,%1,%2,%3}, {%4,%5,%6,%7}, {%8,%9}, {%0,%1,%2,%3};"
        : "+f"(d[0]), "+f"(d[1]), "+f"(d[2]), "+f"(d[3])
        : "r"(a[0]), "r"(a[1]), "r"(a[2]), "r"(a[3]), "r"(b0), "r"(b1));
}

// ---------------------------------------------------------------------------
// Aux kernels (fused single pass over K; unchanged)
// ---------------------------------------------------------------------------
__global__ void convert_norm_kernel(const float* __restrict__ X,
                                    __half* __restrict__ Xh,
                                    float* __restrict__ ninv) {
    int row  = blockIdx.x * 8 + (threadIdx.x >> 5);
    int lane = threadIdx.x & 31;
    const float4* xp = (const float4*)(X + (size_t)row * DIM);
    __half2* op = (__half2*)(Xh + (size_t)row * DIM);
    float s = 0.f;
#pragma unroll
    for (int i = 0; i < 8; i++) {
        float4 v = xp[lane + 32 * i];
        s += v.x * v.x + v.y * v.y + v.z * v.z + v.w * v.w;
        op[(lane + 32 * i) * 2]     = __floats2half2_rn(v.x, v.y);
        op[(lane + 32 * i) * 2 + 1] = __floats2half2_rn(v.z, v.w);
    }
#pragma unroll
    for (int o = 16; o > 0; o >>= 1) s += __shfl_xor_sync(0xffffffffu, s, o);
    if (lane == 0) ninv[row] = rsqrtf(s);
}

__global__ void fuse_k_kernel(const float* __restrict__ K) {
    __shared__ float tile[32][33];
    int n0 = blockIdx.x * 32, k0 = blockIdx.y * 32;
    int tx = threadIdx.x, ty = threadIdx.y;
#pragma unroll
    for (int i = 0; i < 4; i++) {
        int k = k0 + ty + 8 * i;
        float v = K[(size_t)k * DIM + n0 + tx];
        g_Kh[(size_t)k * DIM + n0 + tx] = __float2half(v);
        tile[ty + 8 * i][tx] = v;
    }
    __syncthreads();
#pragma unroll
    for (int i = 0; i < 4; i++)
        g_Vt[(size_t)(n0 + ty + 8 * i) * NK + k0 + tx] =
            __float2half(tile[tx][ty + 8 * i]);
    if (ty == 0) {
        float s = 0.f;
#pragma unroll
        for (int j = 0; j < 32; j++) { float v = tile[tx][j]; s += v * v; }
        g_knpart[blockIdx.x][k0 + tx] = s;
    } else if (ty == 1) {
        float s = 0.f;
#pragma unroll
        for (int j = 0; j < 32; j++) s += tile[j][tx];
        g_colpart[blockIdx.y][n0 + tx] = s;
    }
}

__global__ void kfin_kernel() {
    int gid = blockIdx.x * 256 + threadIdx.x;
    float s = 0.f;
#pragma unroll
    for (int j = 0; j < 32; j++) s += g_knpart[j][gid];
    g_kninv[gid] = rsqrtf(s);
    if (gid < DIM) {
        float c = 0.f;
        for (int j = 0; j < 256; j++) c += g_colpart[j][gid];
        g_colsum[gid] = c;
    }
}

__global__ void rowsum_fin_kernel() {
    int m = blockIdx.x * 256 + threadIdx.x;
    float s = (float)NK;
#pragma unroll
    for (int j = 0; j < NK / 128; j++) s += g_rpart[j][m];
    g_rsum[m] = s;
}

// ---------------------------------------------------------------------------
// HMMA fp16 GEMM: 128x128x64 tile, 512 threads, 3-stage cp.async, 1 CTA/SM.
// Warp grid 4(m) x 4(n); warp tile 32m x 32n -> acc = 32 regs/thread, which
// frees registers for EXPLICIT fragment double-buffering: kk+1's 4 LDSM are
// issued before kk's 8 MMAs, hiding the LDSM->MMA scoreboard stall that
// capped tensor pipe at ~51%.
//   MODE 0: A=Qh[m][k], B=Kh[n][k]; epi r=exp(acc*qninv*kninv)-1 -> g_R,
//           fused per-CTA row sums -> g_rpart[blockIdx.x][m]
//   MODE 1: A=R[m][k],  B=Vt[n][k]; epi (acc + colsum[n]) / rsum[m] -> Cout
// ---------------------------------------------------------------------------
#define BM 128
#define BN 128
#define BK 64
#define STAGES 3
#define PITCHB 144                             // bytes per 64-half row
#define ST_A_BYTES (BM * PITCHB)               // 18432
#define ST_BYTES   (2 * ST_A_BYTES)            // 36864 (A + B)
#define SMEM_BYTES (STAGES * ST_BYTES + 2048)  // 112640 (stages + rp_s)

template <int MODE>
__global__ __launch_bounds__(512, 1) void hgemm_kernel(
    const __half* __restrict__ A, const __half* __restrict__ B,
    int lda, int ldb, int kdim, float* __restrict__ Cout) {
    extern __shared__ char smem[];
    const uint32_t sbase = smem_u32(smem);
    const int t = threadIdx.x;
    const int m0 = blockIdx.y * BM, n0 = blockIdx.x * BN;
    const int lane = t & 31, w = t >> 5;
    const int wm = w >> 2, wn = w & 3;          // 4 x 4 warp grid; tile 32m x 32n
    const int lrow = lane & 15, lcol = (lane >> 4) * 16;

    // Per-warp LDSM base offsets (within a stage), kk adds +32 bytes.
    uint32_t a_off[2], b_off[2];
#pragma unroll
    for (int x = 0; x < 2; x++) {
        a_off[x] = (wm * 32 + x * 16 + lrow) * PITCHB + lcol;
        b_off[x] = (wn * 32 + x * 16 + lrow) * PITCHB + lcol;
    }

    // Load geometry: per operand 128 rows x 8 chunks(16B) = 1024; 512 threads
    // do 2 (row, chunk) pairs per operand per stage.
    const int r_ld = t >> 3;                    // 0..63 base row
    const int c_ld = t & 7;
    const __half* aptr[2];
    const __half* bptr[2];
    uint32_t s_off[2];
#pragma unroll
    for (int j = 0; j < 2; j++) {
        int r = r_ld + 64 * j;
        aptr[j] = A + (size_t)(m0 + r) * lda + c_ld * 8;
        bptr[j] = B + (size_t)(n0 + r) * ldb + c_ld * 8;
        s_off[j] = r * PITCHB + c_ld * 16;
    }

    auto load_stage = [&](int ci, int st) {
        uint32_t sa = sbase + st * ST_BYTES;
        uint32_t sb = sa + ST_A_BYTES;
        int k0 = ci * BK;
#pragma unroll
        for (int j = 0; j < 2; j++) {
            cp16(sa + s_off[j], aptr[j] + k0);
            cp16(sb + s_off[j], bptr[j] + k0);
        }
    };

    float acc[2][4][4] = {};
    uint32_t af[2][2][4], bfr[2][2][4];         // double-buffered fragments

    const int KT = kdim / BK;
    load_stage(0, 0); CP_COMMIT();
    load_stage(1, 1); CP_COMMIT();

    for (int i = 0; i < KT; i++) {
        CP_WAIT(1);
        __syncthreads();
        if (i + 2 < KT) load_stage(i + 2, (i + 2) % STAGES);
        CP_COMMIT();

        uint32_t sa = sbase + (i % STAGES) * ST_BYTES;
        uint32_t sb = sa + ST_A_BYTES;

        // prime kk=0 fragments
        ldsm_x4(af[0][0],  sa + a_off[0]);
        ldsm_x4(af[0][1],  sa + a_off[1]);
        ldsm_x4(bfr[0][0], sb + b_off[0]);
        ldsm_x4(bfr[0][1], sb + b_off[1]);

#pragma unroll
        for (int kk = 0; kk < 4; kk++) {
            int cur = kk & 1, nxt = cur ^ 1;
            if (kk < 3) {                       // prefetch kk+1 before MMAs
                uint32_t o = (kk + 1) * 32;
                ldsm_x4(af[nxt][0],  sa + a_off[0] + o);
                ldsm_x4(af[nxt][1],  sa + a_off[1] + o);
                ldsm_x4(bfr[nxt][0], sb + b_off[0] + o);
                ldsm_x4(bfr[nxt][1], sb + b_off[1] + o);
            }
#pragma unroll
            for (int mi = 0; mi < 2; mi++)
#pragma unroll
                for (int ni = 0; ni < 2; ni++) {
                    mma16816(acc[mi][2 * ni],     af[cur][mi], bfr[cur][ni][0], bfr[cur][ni][2]);
                    mma16816(acc[mi][2 * ni + 1], af[cur][mi], bfr[cur][ni][1], bfr[cur][ni][3]);
                }
        }
    }

    // ---- Epilogue ----
    const int g = lane >> 2, q = lane & 3;
    const int rbase = m0 + wm * 32;
    const int cbase = n0 + wn * 32;

    if (MODE == 0) {
        float* rp_s = (float*)(smem + STAGES * ST_BYTES);   // [4][128]
        float rs[2][2] = {};
        float kn[4][2];
#pragma unroll
        for (int nj = 0; nj < 4; nj++) {
            int c = cbase + nj * 8 + q * 2;
            kn[nj][0] = g_kninv[c]; kn[nj][1] = g_kninv[c + 1];
        }
#pragma unroll
        for (int mi = 0; mi < 2; mi++) {
            int r0 = rbase + mi * 16 + g;
            float qi0 = g_qninv[r0], qi1 = g_qninv[r0 + 8];
            __half2* d0 = (__half2*)(g_R + (size_t)r0 * NK);
            __half2* d1 = (__half2*)(g_R + (size_t)(r0 + 8) * NK);
#pragma unroll
            for (int nj = 0; nj < 4; nj++) {
                int c = cbase + nj * 8 + q * 2;
                float e00 = __expf(acc[mi][nj][0] * qi0 * kn[nj][0]) - 1.f;
                float e01 = __expf(acc[mi][nj][1] * qi0 * kn[nj][1]) - 1.f;
                float e10 = __expf(acc[mi][nj][2] * qi1 * kn[nj][0]) - 1.f;
                float e11 = __expf(acc[mi][nj][3] * qi1 * kn[nj][1]) - 1.f;
                rs[mi][0] += e00 + e01;
                rs[mi][1] += e10 + e11;
                d0[c >> 1] = __floats2half2_rn(e00, e01);
                d1[c >> 1] = __floats2half2_rn(e10, e11);
            }
        }
#pragma unroll
        for (int mi = 0; mi < 2; mi++)
#pragma unroll
            for (int h = 0; h < 2; h++) {
                float v = rs[mi][h];
                v += __shfl_xor_sync(0xffffffffu, v, 1);
                v += __shfl_xor_sync(0xffffffffu, v, 2);
                rs[mi][h] = v;
            }
        if (q == 0) {
#pragma unroll
            for (int mi = 0; mi < 2; mi++)
#pragma unroll
                for (int h = 0; h < 2; h++)
                    rp_s[wn * 128 + wm * 32 + mi * 16 + h * 8 + g] = rs[mi][h];
        }
        __syncthreads();
        if (t < 128)
            g_rpart[blockIdx.x][m0 + t] =
                (rp_s[t] + rp_s[128 + t]) + (rp_s[256 + t] + rp_s[384 + t]);
    } else {
#pragma unroll
        for (int mi = 0; mi < 2; mi++) {
            int r0 = rbase + mi * 16 + g;
            float ri0 = 1.0f / g_rsum[r0], ri1 = 1.0f / g_rsum[r0 + 8];
            float* d0 = Cout + (size_t)r0 * DIM;
            float* d1 = Cout + (size_t)(r0 + 8) * DIM;
#pragma unroll
            for (int nj = 0; nj < 4; nj++) {
                int c = cbase + nj * 8 + q * 2;
                float cs0 = g_colsum[c], cs1 = g_colsum[c + 1];
                *(float2*)(d0 + c) = make_float2((acc[mi][nj][0] + cs0) * ri0,
                                                 (acc[mi][nj][1] + cs1) * ri0);
                *(float2*)(d1 + c) = make_float2((acc[mi][nj][2] + cs0) * ri1,
                                                 (acc[mi][nj][3] + cs1) * ri1);
            }
        }
    }
}

// ---------------------------------------------------------------------------
// Launch
// ---------------------------------------------------------------------------
extern "C" void kernel_launch(void* const* d_in, const int* in_sizes, int n_in,
                              void* d_out, int out_size) {
    const float* Q = (const float*)d_in[0];   // [4096, 1024]
    const float* K = (const float*)d_in[1];   // [8192, 1024] (keys == values)
    float* out = (float*)d_out;               // [4096, 1024]
    (void)in_sizes; (void)n_in; (void)out_size;

    void *Qh, *Kh, *Vt, *R, *qn;
    cudaGetSymbolAddress(&Qh, g_Qh);
    cudaGetSymbolAddress(&Kh, g_Kh);
    cudaGetSymbolAddress(&Vt, g_Vt);
    cudaGetSymbolAddress(&R,  g_R);
    cudaGetSymbolAddress(&qn, g_qninv);

    cudaFuncSetAttribute(hgemm_kernel<0>, cudaFuncAttributeMaxDynamicSharedMemorySize, SMEM_BYTES);
    cudaFuncSetAttribute(hgemm_kernel<1>, cudaFuncAttributeMaxDynamicSharedMemorySize, SMEM_BYTES);

    convert_norm_kernel<<<NQ / 8, 256>>>(Q, (__half*)Qh, (float*)qn);
    fuse_k_kernel<<<dim3(DIM / 32, NK / 32), dim3(32, 8)>>>(K);
    kfin_kernel<<<NK / 256, 256>>>();

    // GEMM1: R = exp(cos(Q,K)) - 1   [4096 x 8192] (+ fused row partials)
    hgemm_kernel<0><<<dim3(NK / BN, NQ / BM), 512, SMEM_BYTES>>>(
        (const __half*)Qh, (const __half*)Kh, DIM, DIM, DIM, nullptr);

    rowsum_fin_kernel<<<NQ / 256, 256>>>();

    // GEMM2: out = (R . V + colsumV) / rsum   [4096 x 1024]
    hgemm_kernel<1><<<dim3(DIM / BN, NQ / BM), 512, SMEM_BYTES>>>(
        (const __half*)R, (const __half*)Vt, NK, NK, NK, out);
}